// round 12
// baseline (speedup 1.0000x reference)
#include <cuda_runtime.h>
#include <math.h>

#define NB 2
#define NN 768
#define GRID 576
#define TPB 128
#define NEG08 0.8f
#define EPSV 1e-6f
#define FEPS 1e-12f
#define NCOEF 13

// ---------------- scratch (device globals) ---------------------------------
__device__ float g_qx[NB * 96 * NN];        // Qx   [row][n]
__device__ float g_score[NB * NN * NN];     // 2*inner - sq[m]
__device__ float g_mb[NB * NN * 32 * 12];   // m-side: [point][o][12]
__device__ float g_nb[NB * NN * 32 * 12];   // n-side
__device__ float g_part[192 * 32];          // moments [row][0..12=M,13..25=G]
__device__ unsigned g_barcnt;               // monotonic barrier counter

__constant__ float c_invf[NCOEF] = {
    1.0f, 1.0f, 0.5f, 1.6666666667e-1f, 4.1666666667e-2f, 8.3333333333e-3f,
    1.3888888889e-3f, 1.9841269841e-4f, 2.4801587302e-5f, 2.7557319224e-6f,
    2.7557319224e-7f, 2.5052108385e-8f, 2.0876756988e-9f};

// ---------------- software grid barrier (proven at GRID=576, 4/SM) ---------
__device__ __forceinline__ void grid_bar() {
    __syncthreads();
    __threadfence();
    if (threadIdx.x == 0) {
        unsigned ticket = atomicAdd(&g_barcnt, 1u);
        unsigned target = (ticket / GRID + 1u) * GRID;
        while (atomicAdd(&g_barcnt, 0u) < target) __nanosleep(64);
        __threadfence();
    }
    __syncthreads();
}

// ---------------- phase 1a: gram half-tile (32n x 64m) ---------------------
__device__ void gram_unit(int u, const float* __restrict__ y,
                          unsigned char* sm) {
    float (*As)[32] = (float (*)[32])sm;            // 4KB
    float (*Bs)[64] = (float (*)[64])(sm + 4096);   // 8KB
    int pairId = u >> 1, half = u & 1;
    int b = pairId / 78, pr = pairId % 78;
    int i = 0;
    while (pr >= 12 - i) { pr -= 12 - i; i++; }
    int j = i + pr;
    int n0 = i * 64 + half * 32, m0 = j * 64;
    int tid = threadIdx.x;
    int tx = tid & 15, ty = tid >> 4;
    float acc[4][4] = {};
    float asq[4] = {}, bsq[4] = {};
    for (int jc = 0; jc < 96; jc += 32) {
        __syncthreads();
        for (int e = tid; e < 1024; e += TPB) {
            int kk = e >> 5, rr = e & 31;
            As[kk][rr] = y[(b * 96 + jc + kk) * NN + n0 + rr];
        }
        for (int e = tid; e < 2048; e += TPB) {
            int kk = e >> 6, rr = e & 63;
            Bs[kk][rr] = y[(b * 96 + jc + kk) * NN + m0 + rr];
        }
        __syncthreads();
#pragma unroll
        for (int kk = 0; kk < 32; kk++) {
            float4 a4 = *(float4*)&As[kk][ty * 4];
            float4 b4 = *(float4*)&Bs[kk][tx * 4];
            float av[4] = {a4.x, a4.y, a4.z, a4.w};
            float bv[4] = {b4.x, b4.y, b4.z, b4.w};
#pragma unroll
            for (int q = 0; q < 4; q++) {
                asq[q] = fmaf(av[q], av[q], asq[q]);
                bsq[q] = fmaf(bv[q], bv[q], bsq[q]);
            }
#pragma unroll
            for (int p = 0; p < 4; p++)
#pragma unroll
                for (int q = 0; q < 4; q++)
                    acc[p][q] = fmaf(av[p], bv[q], acc[p][q]);
        }
    }
#pragma unroll
    for (int p = 0; p < 4; p++) {
        int n = n0 + ty * 4 + p;
        float4 o;
        o.x = 2.f * acc[p][0] - bsq[0];
        o.y = 2.f * acc[p][1] - bsq[1];
        o.z = 2.f * acc[p][2] - bsq[2];
        o.w = 2.f * acc[p][3] - bsq[3];
        *(float4*)&g_score[((size_t)(b * NN + n)) * NN + m0 + tx * 4] = o;
    }
    if (i != j) {
#pragma unroll
        for (int q = 0; q < 4; q++) {
            int m = m0 + tx * 4 + q;
            float4 o;
            o.x = 2.f * acc[0][q] - asq[0];
            o.y = 2.f * acc[1][q] - asq[1];
            o.z = 2.f * acc[2][q] - asq[2];
            o.w = 2.f * acc[3][q] - asq[3];
            *(float4*)&g_score[((size_t)(b * NN + m)) * NN + n0 + ty * 4] = o;
        }
    }
}

// ---------------- phase 1b: per-point precompute (warp per point) ----------
__device__ void pre_unit(int p, const float* __restrict__ x,
                         const float* __restrict__ y,
                         const float* __restrict__ Wqf,
                         const float* __restrict__ Wqd,
                         const float* __restrict__ Wkf,
                         const float* __restrict__ Wkd,
                         const float* __restrict__ Wvf,
                         const float* __restrict__ Wvd,
                         unsigned char* sm) {
    float2 (*sQ)[32] = (float2 (*)[32])sm;                 // 8KB
    float4 (*sM)[32] = (float4 (*)[32])(sm + 8192);        // 16KB
    float4 (*sN)[32] = (float4 (*)[32])(sm + 24576);       // 16KB
    float (*xs)[96]  = (float (*)[96])(sm + 40960);        // 1.5KB
    float (*ys)[96]  = (float (*)[96])(sm + 42496);        // 1.5KB
    int tid = threadIdx.x;
    __syncthreads();     // protect smem from previous unit's readers
    for (int q = tid; q < 1024; q += TPB) {
        int o = q >> 5, c = q & 31;
        sQ[c][o] = make_float2(Wqf[q], Wqd[q]);
        float kfl = Wkf[o * 64 + c], kdl = Wkd[o * 64 + c];
        float vfl = Wvf[o * 64 + c], vdl = Wvd[o * 64 + c];
        sM[c][o] = make_float4(kfl, kdl, vfl, vdl);
        sN[c][o] = make_float4(Wkf[o * 64 + 32 + c] - kfl,
                               Wkd[o * 64 + 32 + c] - kdl,
                               Wvf[o * 64 + 32 + c] - vfl,
                               Wvd[o * 64 + 32 + c] - vdl);
    }
    int wid = tid >> 5, lane = tid & 31;
    int pt = p * 4 + wid;
    int b = pt / NN, n = pt % NN;
    for (int e = lane; e < 96; e += 32) {
        xs[wid][e] = x[(b * 96 + e) * NN + n];
        ys[wid][e] = y[(b * 96 + e) * NN + n];
    }
    __syncthreads();

    float qp[3] = {}, qd[3] = {};
    float am[4][3] = {}, an[4][3] = {};
#pragma unroll
    for (int c = 0; c < 32; c++) {
        float2 q = sQ[c][lane];
        float4 mv = sM[c][lane];
        float4 nv = sN[c][lane];
        float mvv[4] = {mv.x, mv.y, mv.z, mv.w};
        float nvv[4] = {nv.x, nv.y, nv.z, nv.w};
#pragma unroll
        for (int d = 0; d < 3; d++) {
            float xv = xs[wid][c * 3 + d];
            float yv = ys[wid][c * 3 + d];
            qp[d] = fmaf(q.x, xv, qp[d]);
            qd[d] = fmaf(q.y, xv, qd[d]);
#pragma unroll
            for (int a = 0; a < 4; a++) {
                am[a][d] = fmaf(mvv[a], yv, am[a][d]);
                an[a][d] = fmaf(nvv[a], yv, an[a][d]);
            }
        }
    }
    float dot = qp[0] * qd[0] + qp[1] * qd[1] + qp[2] * qd[2];
    float dsq = qd[0] * qd[0] + qd[1] * qd[1] + qd[2] * qd[2];
    if (dot < 0.f) {
        float f = NEG08 * dot / (dsq + EPSV);
        qp[0] -= f * qd[0]; qp[1] -= f * qd[1]; qp[2] -= f * qd[2];
    }
    float nsq = qp[0] * qp[0] + qp[1] * qp[1] + qp[2] * qp[2];
    float nrm = sqrtf(nsq);
    float chsq = nsq;
#pragma unroll
    for (int off = 16; off; off >>= 1)
        chsq += __shfl_xor_sync(0xffffffffu, chsq, off);
    float chn = sqrtf(chsq);
    float fac = (nrm / fmaxf(nrm, FEPS)) / fmaxf(chn, FEPS);
#pragma unroll
    for (int d = 0; d < 3; d++)
        g_qx[(b * 96 + lane * 3 + d) * NN + n] = qp[d] * fac;

    size_t base = ((size_t)(b * NN + n) * 32 + lane) * 12;
    float4* mb4 = (float4*)(g_mb + base);
    float4* nb4 = (float4*)(g_nb + base);
    mb4[0] = make_float4(am[0][0], am[0][1], am[0][2], am[1][0]);
    mb4[1] = make_float4(am[1][1], am[1][2], am[2][0], am[2][1]);
    mb4[2] = make_float4(am[2][2], am[3][0], am[3][1], am[3][2]);
    nb4[0] = make_float4(an[0][0], an[0][1], an[0][2], an[1][0]);
    nb4[1] = make_float4(an[1][1], an[1][2], an[2][0], an[2][1]);
    nb4[2] = make_float4(an[2][2], an[3][0], an[3][1], an[3][2]);
}

// ---------------- phase 2: top-16 + K/V + moment atomics (fused) -----------
__device__ void knn_phase() {
    int tid = threadIdx.x;
    int wid = tid >> 5, lane = tid & 31;
    int gw = blockIdx.x * 4 + wid;
    if (gw >= NB * NN) return;
    int b = gw / NN, n = gw % NN;

    const float4* srow4 = (const float4*)(g_score + (size_t)(b * NN + n) * NN);
    unsigned mono_[24];
#pragma unroll
    for (int j = 0; j < 6; j++) {
        float4 f = srow4[lane + j * 32];
        float fv[4] = {f.x, f.y, f.z, f.w};
#pragma unroll
        for (int t = 0; t < 4; t++) {
            unsigned uu = __float_as_uint(fv[t]);
            mono_[j * 4 + t] = (uu & 0x80000000u) ? ~uu : (uu | 0x80000000u);
        }
    }
    // n-side vectors (issue loads early)
    size_t nbase = ((size_t)(b * NN + n) * 32 + lane) * 12;
    const float4* nb4g = (const float4*)(g_nb + nbase);
    float4 nv0 = nb4g[0], nv1 = nb4g[1], nv2 = nb4g[2];
    float nbv[12] = {nv0.x, nv0.y, nv0.z, nv0.w, nv1.x, nv1.y, nv1.z, nv1.w,
                     nv2.x, nv2.y, nv2.z, nv2.w};

    // ---- per-lane top-3 cache: composite key (value desc, index asc) ----
    unsigned c0 = 0, c1 = 0, c2 = 0;
    int g0 = 0x7fffffff, g1 = 0x7fffffff, g2 = 0x7fffffff;
    {
        unsigned lv = 0xffffffffu; int lg = -1;
#pragma unroll
        for (int q = 0; q < 24; q++) {
            unsigned uq = mono_[q];
            int gq = 4 * (lane + (q >> 2) * 32) + (q & 3);
            bool keep = (uq < lv) || (uq == lv && gq > lg);
            if (keep) {
                if (uq > c0 || (uq == c0 && gq < g0)) {
                    c2 = c1; g2 = g1; c1 = c0; g1 = g0; c0 = uq; g0 = gq;
                } else if (uq > c1 || (uq == c1 && gq < g1)) {
                    c2 = c1; g2 = g1; c1 = uq; g1 = gq;
                } else if (uq > c2 || (uq == c2 && gq < g2)) {
                    c2 = uq; g2 = gq;
                }
            }
        }
    }
    // ---- selection loop ----
    int mymsel = 0;
    for (int it = 0; it < 16; it++) {
        unsigned wm = __reduce_max_sync(0xffffffffu, c0);
        unsigned cand = (c0 == wm) ? (unsigned)g0 : 0xffffffffu;
        int m = (int)__reduce_min_sync(0xffffffffu, cand);
        if (lane == it) mymsel = m;
        if (c0 == wm && g0 == m) {
            c0 = c1; g0 = g1; c1 = c2; g1 = g2; c2 = 0; g2 = 0x7fffffff;
            if (c0 == 0) {   // cache empty: exact rebuild after key (wm, m)
                unsigned lv = wm; int lg = m;
#pragma unroll
                for (int q = 0; q < 24; q++) {
                    unsigned uq = mono_[q];
                    int gq = 4 * (lane + (q >> 2) * 32) + (q & 3);
                    bool keep = (uq < lv) || (uq == lv && gq > lg);
                    if (keep) {
                        if (uq > c0 || (uq == c0 && gq < g0)) {
                            c2 = c1; g2 = g1; c1 = c0; g1 = g0; c0 = uq; g0 = gq;
                        } else if (uq > c1 || (uq == c1 && gq < g1)) {
                            c2 = c1; g2 = g1; c1 = uq; g1 = gq;
                        } else if (uq > c2 || (uq == c2 && gq < g2)) {
                            c2 = uq; g2 = gq;
                        }
                    }
                }
            }
        }
    }

    // ---- K/V: groups of 4 neighbors, batched loads + interleaved cevn ----
    float aK[3] = {}, aV[3] = {};
#pragma unroll
    for (int g = 0; g < 4; g++) {
        float4 v[4][3];
#pragma unroll
        for (int t = 0; t < 4; t++) {
            int m = __shfl_sync(0xffffffffu, mymsel, g * 4 + t);
            size_t mbase = ((size_t)(b * NN + m) * 32 + lane) * 12;
            const float4* mb4 = (const float4*)(g_mb + mbase);
            v[t][0] = mb4[0]; v[t][1] = mb4[1]; v[t][2] = mb4[2];
        }
        float Kp[4][3], chsq[4], nsql[4];
#pragma unroll
        for (int t = 0; t < 4; t++) {
            float Kd[3];
            Kp[t][0] = v[t][0].x + nbv[0];
            Kp[t][1] = v[t][0].y + nbv[1];
            Kp[t][2] = v[t][0].z + nbv[2];
            Kd[0] = v[t][0].w + nbv[3];
            Kd[1] = v[t][1].x + nbv[4];
            Kd[2] = v[t][1].y + nbv[5];
            float dot = Kp[t][0] * Kd[0] + Kp[t][1] * Kd[1] + Kp[t][2] * Kd[2];
            float dsq = Kd[0] * Kd[0] + Kd[1] * Kd[1] + Kd[2] * Kd[2];
            if (dot < 0.f) {
                float f = NEG08 * dot / (dsq + EPSV);
                Kp[t][0] -= f * Kd[0]; Kp[t][1] -= f * Kd[1]; Kp[t][2] -= f * Kd[2];
            }
            nsql[t] = Kp[t][0] * Kp[t][0] + Kp[t][1] * Kp[t][1] + Kp[t][2] * Kp[t][2];
            chsq[t] = nsql[t];
        }
#pragma unroll
        for (int off = 16; off; off >>= 1) {
#pragma unroll
            for (int t = 0; t < 4; t++)
                chsq[t] += __shfl_xor_sync(0xffffffffu, chsq[t], off);
        }
#pragma unroll
        for (int t = 0; t < 4; t++) {
            float nrm = sqrtf(nsql[t]);
            float chn = sqrtf(chsq[t]);
            float fac = (nrm / fmaxf(nrm, FEPS)) / fmaxf(chn, FEPS);
            aK[0] += Kp[t][0] * fac;
            aK[1] += Kp[t][1] * fac;
            aK[2] += Kp[t][2] * fac;
        }
#pragma unroll
        for (int t = 0; t < 4; t++) {
            float Vp[3], Vd[3];
            Vp[0] = v[t][1].z + nbv[6];
            Vp[1] = v[t][1].w + nbv[7];
            Vp[2] = v[t][2].x + nbv[8];
            Vd[0] = v[t][2].y + nbv[9];
            Vd[1] = v[t][2].z + nbv[10];
            Vd[2] = v[t][2].w + nbv[11];
            float dotv = Vp[0] * Vd[0] + Vp[1] * Vd[1] + Vp[2] * Vd[2];
            float dsqv = Vd[0] * Vd[0] + Vd[1] * Vd[1] + Vd[2] * Vd[2];
            if (dotv < 0.f) {
                float f = NEG08 * dotv / (dsqv + EPSV);
                Vp[0] -= f * Vd[0]; Vp[1] -= f * Vd[1]; Vp[2] -= f * Vd[2];
            }
            aV[0] += Vp[0]; aV[1] += Vp[1]; aV[2] += Vp[2];
        }
    }

    // ---- moment contributions: lane owns rows (b*96 + lane*3 + d) ----
#pragma unroll
    for (int d = 0; d < 3; d++) {
        float k = aK[d], vv = aV[d];
        float* rp = g_part + (b * 96 + lane * 3 + d) * 32;
        float p = 1.f;
#pragma unroll
        for (int j = 0; j < NCOEF; j++) {
            atomicAdd(rp + j, p);
            atomicAdd(rp + NCOEF + j, vv * p);
            p *= k;
        }
    }
}

// ---------------- phase 3: evaluate rank-1 softmax (576 units) -------------
__device__ void eval_phase(const float* __restrict__ x,
                           float* __restrict__ out, unsigned char* sm) {
    float* sMo = (float*)sm;
    float* sGo = (float*)sm + NCOEF;
    int u = blockIdx.x, tid = threadIdx.x;
    int row = u / 3, third = u % 3;
    if (tid < NCOEF) sMo[tid] = g_part[row * 32 + tid] * c_invf[tid];
    else if (tid < 2 * NCOEF) sGo[tid - NCOEF] = g_part[row * 32 + tid] * c_invf[tid - NCOEF];
    __syncthreads();
    float cM[NCOEF], cG[NCOEF];
#pragma unroll
    for (int jj = 0; jj < NCOEF; jj++) { cM[jj] = sMo[jj]; cG[jj] = sGo[jj]; }

    const float scale = 0.10206207262f;  // 1/sqrt(96)
#pragma unroll
    for (int j = 0; j < 2; j++) {
        size_t idx = (size_t)row * NN + third * 256 + tid + j * 128;
        float t = g_qx[idx] * scale;
        float den = cM[NCOEF - 1], num = cG[NCOEF - 1];
#pragma unroll
        for (int jj = NCOEF - 2; jj >= 0; jj--) {
            den = fmaf(den, t, cM[jj]);
            num = fmaf(num, t, cG[jj]);
        }
        out[idx] = x[idx] + num / den;
    }
}

// ---------------- fused mega-kernel ----------------------------------------
__global__ void __launch_bounds__(TPB, 4)
fused_kernel(const float* __restrict__ x, const float* __restrict__ y,
             const float* __restrict__ Wqf, const float* __restrict__ Wqd,
             const float* __restrict__ Wkf, const float* __restrict__ Wkd,
             const float* __restrict__ Wvf, const float* __restrict__ Wvd,
             float* __restrict__ out) {
    __shared__ __align__(16) unsigned char sm[44032];

    int u = blockIdx.x;
    // zero moment accumulators (visible to knn via the grid barrier)
    if (u < 192 && threadIdx.x < 32) g_part[u * 32 + threadIdx.x] = 0.f;

    if (u < 312) {
        gram_unit(u, y, sm);
    } else {
        for (int pu = u - 312; pu < 384; pu += 264)
            pre_unit(pu, x, y, Wqf, Wqd, Wkf, Wkd, Wvf, Wvd, sm);
    }
    grid_bar();
    knn_phase();
    grid_bar();
    eval_phase(x, out, sm);
}

// ---------------- launcher --------------------------------------------------
extern "C" void kernel_launch(void* const* d_in, const int* in_sizes, int n_in,
                              void* d_out, int out_size) {
    const float* x   = (const float*)d_in[0];
    const float* y   = (const float*)d_in[1];
    const float* Wqf = (const float*)d_in[2];
    const float* Wqd = (const float*)d_in[3];
    const float* Wkf = (const float*)d_in[4];
    const float* Wkd = (const float*)d_in[5];
    const float* Wvf = (const float*)d_in[6];
    const float* Wvd = (const float*)d_in[7];
    float* out = (float*)d_out;

    fused_kernel<<<GRID, TPB>>>(x, y, Wqf, Wqd, Wkf, Wkd, Wvf, Wvd, out);
}

// round 13
// speedup vs baseline: 3.2737x; 3.2737x over previous
#include <cuda_runtime.h>
#include <math.h>

#define NB 2
#define NN 768
#define GRID 576
#define TPB 128
#define NEG08 0.8f
#define EPSV 1e-6f
#define FEPS 1e-12f
#define NCOEF 13

typedef unsigned long long ull;

#define FFMA2(d, a, b, c) \
    asm("fma.rn.f32x2 %0, %1, %2, %3;" : "=l"(d) : "l"(a), "l"(b), "l"(c))
#define PACK2(d, f) \
    asm("mov.b64 %0, {%1, %1};" : "=l"(d) : "r"(__float_as_uint(f)))

__device__ __forceinline__ float lo2(ull v) { return __uint_as_float((unsigned)v); }
__device__ __forceinline__ float hi2(ull v) { return __uint_as_float((unsigned)(v >> 32)); }

// ---------------- scratch (device globals) ---------------------------------
__device__ float g_qx[NB * 96 * NN];        // Qx   [row][n]
__device__ float g_score[NB * NN * NN];     // 2*inner - sq[m]
__device__ float g_mb[NB * NN * 32 * 12];   // m-side: [point][o][12]
__device__ float g_nb[NB * NN * 32 * 12];   // n-side
__device__ float g_ksum[NB * 96 * NN];      // [row][n]
__device__ float g_vsum[NB * 96 * NN];
__device__ unsigned g_barcnt;               // monotonic barrier counter

__constant__ float c_invf[NCOEF] = {
    1.0f, 1.0f, 0.5f, 1.6666666667e-1f, 4.1666666667e-2f, 8.3333333333e-3f,
    1.3888888889e-3f, 1.9841269841e-4f, 2.4801587302e-5f, 2.7557319224e-6f,
    2.7557319224e-7f, 2.5052108385e-8f, 2.0876756988e-9f};

// ---------------- software grid barrier (proven at GRID=576, 4/SM) ---------
__device__ __forceinline__ void grid_bar() {
    __syncthreads();
    __threadfence();
    if (threadIdx.x == 0) {
        unsigned ticket = atomicAdd(&g_barcnt, 1u);
        unsigned target = (ticket / GRID + 1u) * GRID;
        while (atomicAdd(&g_barcnt, 0u) < target) __nanosleep(64);
        __threadfence();
    }
    __syncthreads();
}

// ---------------- phase 1a: gram half-tile (32n x 64m), f32x2 FMA ----------
__device__ void gram_unit(int u, const float* __restrict__ y,
                          unsigned char* sm) {
    float (*As)[32] = (float (*)[32])sm;            // 4KB
    float (*Bs)[64] = (float (*)[64])(sm + 4096);   // 8KB
    int pairId = u >> 1, half = u & 1;
    int b = pairId / 78, pr = pairId % 78;
    int i = 0;
    while (pr >= 12 - i) { pr -= 12 - i; i++; }
    int j = i + pr;
    int n0 = i * 64 + half * 32, m0 = j * 64;
    int tid = threadIdx.x;
    int tx = tid & 15, ty = tid >> 4;
    ull acc2[2][4] = {};      // p-pairs x q
    ull asq2[2] = {}, bsq2[2] = {};
    for (int jc = 0; jc < 96; jc += 32) {
        __syncthreads();
        for (int e = tid; e < 1024; e += TPB) {
            int kk = e >> 5, rr = e & 31;
            As[kk][rr] = y[(b * 96 + jc + kk) * NN + n0 + rr];
        }
        for (int e = tid; e < 2048; e += TPB) {
            int kk = e >> 6, rr = e & 63;
            Bs[kk][rr] = y[(b * 96 + jc + kk) * NN + m0 + rr];
        }
        __syncthreads();
#pragma unroll
        for (int kk = 0; kk < 32; kk++) {
            ulonglong2 a2 = *(ulonglong2*)&As[kk][ty * 4];   // {a0,a1},{a2,a3}
            ulonglong2 b2 = *(ulonglong2*)&Bs[kk][tx * 4];
            ull av2[2] = {a2.x, a2.y};
            float4 b4 = *(float4*)&Bs[kk][tx * 4];
            ull bd[4];
            PACK2(bd[0], b4.x); PACK2(bd[1], b4.y);
            PACK2(bd[2], b4.z); PACK2(bd[3], b4.w);
            FFMA2(asq2[0], av2[0], av2[0], asq2[0]);
            FFMA2(asq2[1], av2[1], av2[1], asq2[1]);
            FFMA2(bsq2[0], b2.x, b2.x, bsq2[0]);
            FFMA2(bsq2[1], b2.y, b2.y, bsq2[1]);
#pragma unroll
            for (int p2 = 0; p2 < 2; p2++)
#pragma unroll
                for (int q = 0; q < 4; q++)
                    FFMA2(acc2[p2][q], av2[p2], bd[q], acc2[p2][q]);
        }
    }
    float acc[4][4], asq[4], bsq[4];
#pragma unroll
    for (int p2 = 0; p2 < 2; p2++) {
        asq[2 * p2] = lo2(asq2[p2]);
        asq[2 * p2 + 1] = hi2(asq2[p2]);
        bsq[2 * p2] = lo2(bsq2[p2]);
        bsq[2 * p2 + 1] = hi2(bsq2[p2]);
#pragma unroll
        for (int q = 0; q < 4; q++) {
            acc[2 * p2][q] = lo2(acc2[p2][q]);
            acc[2 * p2 + 1][q] = hi2(acc2[p2][q]);
        }
    }
#pragma unroll
    for (int p = 0; p < 4; p++) {
        int n = n0 + ty * 4 + p;
        float4 o;
        o.x = 2.f * acc[p][0] - bsq[0];
        o.y = 2.f * acc[p][1] - bsq[1];
        o.z = 2.f * acc[p][2] - bsq[2];
        o.w = 2.f * acc[p][3] - bsq[3];
        *(float4*)&g_score[((size_t)(b * NN + n)) * NN + m0 + tx * 4] = o;
    }
    if (i != j) {
#pragma unroll
        for (int q = 0; q < 4; q++) {
            int m = m0 + tx * 4 + q;
            float4 o;
            o.x = 2.f * acc[0][q] - asq[0];
            o.y = 2.f * acc[1][q] - asq[1];
            o.z = 2.f * acc[2][q] - asq[2];
            o.w = 2.f * acc[3][q] - asq[3];
            *(float4*)&g_score[((size_t)(b * NN + m)) * NN + n0 + ty * 4] = o;
        }
    }
}

// ---------------- phase 1b: per-point precompute (warp per point) ----------
__device__ void pre_unit(int p, const float* __restrict__ x,
                         const float* __restrict__ y,
                         const float* __restrict__ Wqf,
                         const float* __restrict__ Wqd,
                         const float* __restrict__ Wkf,
                         const float* __restrict__ Wkd,
                         const float* __restrict__ Wvf,
                         const float* __restrict__ Wvd,
                         unsigned char* sm) {
    float2 (*sQ)[32] = (float2 (*)[32])sm;                 // 8KB
    float4 (*sM)[32] = (float4 (*)[32])(sm + 8192);        // 16KB
    float4 (*sN)[32] = (float4 (*)[32])(sm + 24576);       // 16KB
    float (*xs)[96]  = (float (*)[96])(sm + 40960);        // 1.5KB
    float (*ys)[96]  = (float (*)[96])(sm + 42496);        // 1.5KB
    int tid = threadIdx.x;
    __syncthreads();     // protect smem from previous unit's readers
    for (int q = tid; q < 1024; q += TPB) {
        int o = q >> 5, c = q & 31;
        sQ[c][o] = make_float2(Wqf[q], Wqd[q]);
        float kfl = Wkf[o * 64 + c], kdl = Wkd[o * 64 + c];
        float vfl = Wvf[o * 64 + c], vdl = Wvd[o * 64 + c];
        sM[c][o] = make_float4(kfl, kdl, vfl, vdl);
        sN[c][o] = make_float4(Wkf[o * 64 + 32 + c] - kfl,
                               Wkd[o * 64 + 32 + c] - kdl,
                               Wvf[o * 64 + 32 + c] - vfl,
                               Wvd[o * 64 + 32 + c] - vdl);
    }
    int wid = tid >> 5, lane = tid & 31;
    int pt = p * 4 + wid;
    int b = pt / NN, n = pt % NN;
    for (int e = lane; e < 96; e += 32) {
        xs[wid][e] = x[(b * 96 + e) * NN + n];
        ys[wid][e] = y[(b * 96 + e) * NN + n];
    }
    __syncthreads();

    float qp[3] = {}, qd[3] = {};
    float am[4][3] = {}, an[4][3] = {};
#pragma unroll
    for (int c = 0; c < 32; c++) {
        float2 q = sQ[c][lane];
        float4 mv = sM[c][lane];
        float4 nv = sN[c][lane];
        float mvv[4] = {mv.x, mv.y, mv.z, mv.w};
        float nvv[4] = {nv.x, nv.y, nv.z, nv.w};
#pragma unroll
        for (int d = 0; d < 3; d++) {
            float xv = xs[wid][c * 3 + d];
            float yv = ys[wid][c * 3 + d];
            qp[d] = fmaf(q.x, xv, qp[d]);
            qd[d] = fmaf(q.y, xv, qd[d]);
#pragma unroll
            for (int a = 0; a < 4; a++) {
                am[a][d] = fmaf(mvv[a], yv, am[a][d]);
                an[a][d] = fmaf(nvv[a], yv, an[a][d]);
            }
        }
    }
    float dot = qp[0] * qd[0] + qp[1] * qd[1] + qp[2] * qd[2];
    float dsq = qd[0] * qd[0] + qd[1] * qd[1] + qd[2] * qd[2];
    if (dot < 0.f) {
        float f = NEG08 * dot / (dsq + EPSV);
        qp[0] -= f * qd[0]; qp[1] -= f * qd[1]; qp[2] -= f * qd[2];
    }
    float nsq = qp[0] * qp[0] + qp[1] * qp[1] + qp[2] * qp[2];
    float nrm = sqrtf(nsq);
    float chsq = nsq;
#pragma unroll
    for (int off = 16; off; off >>= 1)
        chsq += __shfl_xor_sync(0xffffffffu, chsq, off);
    float chn = sqrtf(chsq);
    float fac = (nrm / fmaxf(nrm, FEPS)) / fmaxf(chn, FEPS);
#pragma unroll
    for (int d = 0; d < 3; d++)
        g_qx[(b * 96 + lane * 3 + d) * NN + n] = qp[d] * fac;

    size_t base = ((size_t)(b * NN + n) * 32 + lane) * 12;
    float4* mb4 = (float4*)(g_mb + base);
    float4* nb4 = (float4*)(g_nb + base);
    mb4[0] = make_float4(am[0][0], am[0][1], am[0][2], am[1][0]);
    mb4[1] = make_float4(am[1][1], am[1][2], am[2][0], am[2][1]);
    mb4[2] = make_float4(am[2][2], am[3][0], am[3][1], am[3][2]);
    nb4[0] = make_float4(an[0][0], an[0][1], an[0][2], an[1][0]);
    nb4[1] = make_float4(an[1][1], an[1][2], an[2][0], an[2][1]);
    nb4[2] = make_float4(an[2][2], an[3][0], an[3][1], an[3][2]);
}

// ---------------- phase 2: warp-per-point top-16 + K/V (fused) -------------
__device__ void knn_phase() {
    int tid = threadIdx.x;
    int wid = tid >> 5, lane = tid & 31;
    int gw = blockIdx.x * 4 + wid;
    if (gw >= NB * NN) return;
    int b = gw / NN, n = gw % NN;

    const float4* srow4 = (const float4*)(g_score + (size_t)(b * NN + n) * NN);
    unsigned mono_[24];
#pragma unroll
    for (int j = 0; j < 6; j++) {
        float4 f = srow4[lane + j * 32];
        float fv[4] = {f.x, f.y, f.z, f.w};
#pragma unroll
        for (int t = 0; t < 4; t++) {
            unsigned uu = __float_as_uint(fv[t]);
            mono_[j * 4 + t] = (uu & 0x80000000u) ? ~uu : (uu | 0x80000000u);
        }
    }
    size_t nbase = ((size_t)(b * NN + n) * 32 + lane) * 12;
    const float4* nb4g = (const float4*)(g_nb + nbase);
    float4 nv0 = nb4g[0], nv1 = nb4g[1], nv2 = nb4g[2];
    float nbv[12] = {nv0.x, nv0.y, nv0.z, nv0.w, nv1.x, nv1.y, nv1.z, nv1.w,
                     nv2.x, nv2.y, nv2.z, nv2.w};

    // ---- per-lane top-3 cache: composite key (value desc, index asc) ----
    unsigned c0 = 0, c1 = 0, c2 = 0;
    int g0 = 0x7fffffff, g1 = 0x7fffffff, g2 = 0x7fffffff;
    {
        unsigned lv = 0xffffffffu; int lg = -1;
#pragma unroll
        for (int q = 0; q < 24; q++) {
            unsigned uq = mono_[q];
            int gq = 4 * (lane + (q >> 2) * 32) + (q & 3);
            bool keep = (uq < lv) || (uq == lv && gq > lg);
            if (keep) {
                if (uq > c0 || (uq == c0 && gq < g0)) {
                    c2 = c1; g2 = g1; c1 = c0; g1 = g0; c0 = uq; g0 = gq;
                } else if (uq > c1 || (uq == c1 && gq < g1)) {
                    c2 = c1; g2 = g1; c1 = uq; g1 = gq;
                } else if (uq > c2 || (uq == c2 && gq < g2)) {
                    c2 = uq; g2 = gq;
                }
            }
        }
    }
    int mymsel = 0;
    for (int it = 0; it < 16; it++) {
        unsigned wm = __reduce_max_sync(0xffffffffu, c0);
        unsigned cand = (c0 == wm) ? (unsigned)g0 : 0xffffffffu;
        int m = (int)__reduce_min_sync(0xffffffffu, cand);
        if (lane == it) mymsel = m;
        if (c0 == wm && g0 == m) {
            c0 = c1; g0 = g1; c1 = c2; g1 = g2; c2 = 0; g2 = 0x7fffffff;
            if (c0 == 0) {
                unsigned lv = wm; int lg = m;
#pragma unroll
                for (int q = 0; q < 24; q++) {
                    unsigned uq = mono_[q];
                    int gq = 4 * (lane + (q >> 2) * 32) + (q & 3);
                    bool keep = (uq < lv) || (uq == lv && gq > lg);
                    if (keep) {
                        if (uq > c0 || (uq == c0 && gq < g0)) {
                            c2 = c1; g2 = g1; c1 = c0; g1 = g0; c0 = uq; g0 = gq;
                        } else if (uq > c1 || (uq == c1 && gq < g1)) {
                            c2 = c1; g2 = g1; c1 = uq; g1 = gq;
                        } else if (uq > c2 || (uq == c2 && gq < g2)) {
                            c2 = uq; g2 = gq;
                        }
                    }
                }
            }
        }
    }

    // ---- K/V: groups of 4 neighbors, batched loads + interleaved cevn ----
    float aK[3] = {}, aV[3] = {};
#pragma unroll
    for (int g = 0; g < 4; g++) {
        float4 v[4][3];
#pragma unroll
        for (int t = 0; t < 4; t++) {
            int m = __shfl_sync(0xffffffffu, mymsel, g * 4 + t);
            size_t mbase = ((size_t)(b * NN + m) * 32 + lane) * 12;
            const float4* mb4 = (const float4*)(g_mb + mbase);
            v[t][0] = mb4[0]; v[t][1] = mb4[1]; v[t][2] = mb4[2];
        }
        float Kp[4][3], chsq[4], nsql[4];
#pragma unroll
        for (int t = 0; t < 4; t++) {
            float Kd[3];
            Kp[t][0] = v[t][0].x + nbv[0];
            Kp[t][1] = v[t][0].y + nbv[1];
            Kp[t][2] = v[t][0].z + nbv[2];
            Kd[0] = v[t][0].w + nbv[3];
            Kd[1] = v[t][1].x + nbv[4];
            Kd[2] = v[t][1].y + nbv[5];
            float dot = Kp[t][0] * Kd[0] + Kp[t][1] * Kd[1] + Kp[t][2] * Kd[2];
            float dsq = Kd[0] * Kd[0] + Kd[1] * Kd[1] + Kd[2] * Kd[2];
            if (dot < 0.f) {
                float f = NEG08 * dot / (dsq + EPSV);
                Kp[t][0] -= f * Kd[0]; Kp[t][1] -= f * Kd[1]; Kp[t][2] -= f * Kd[2];
            }
            nsql[t] = Kp[t][0] * Kp[t][0] + Kp[t][1] * Kp[t][1] + Kp[t][2] * Kp[t][2];
            chsq[t] = nsql[t];
        }
#pragma unroll
        for (int off = 16; off; off >>= 1) {
#pragma unroll
            for (int t = 0; t < 4; t++)
                chsq[t] += __shfl_xor_sync(0xffffffffu, chsq[t], off);
        }
#pragma unroll
        for (int t = 0; t < 4; t++) {
            float nrm = sqrtf(nsql[t]);
            float chn = sqrtf(chsq[t]);
            float fac = (nrm / fmaxf(nrm, FEPS)) / fmaxf(chn, FEPS);
            aK[0] += Kp[t][0] * fac;
            aK[1] += Kp[t][1] * fac;
            aK[2] += Kp[t][2] * fac;
        }
#pragma unroll
        for (int t = 0; t < 4; t++) {
            float Vp[3], Vd[3];
            Vp[0] = v[t][1].z + nbv[6];
            Vp[1] = v[t][1].w + nbv[7];
            Vp[2] = v[t][2].x + nbv[8];
            Vd[0] = v[t][2].y + nbv[9];
            Vd[1] = v[t][2].z + nbv[10];
            Vd[2] = v[t][2].w + nbv[11];
            float dotv = Vp[0] * Vd[0] + Vp[1] * Vd[1] + Vp[2] * Vd[2];
            float dsqv = Vd[0] * Vd[0] + Vd[1] * Vd[1] + Vd[2] * Vd[2];
            if (dotv < 0.f) {
                float f = NEG08 * dotv / (dsqv + EPSV);
                Vp[0] -= f * Vd[0]; Vp[1] -= f * Vd[1]; Vp[2] -= f * Vd[2];
            }
            aV[0] += Vp[0]; aV[1] += Vp[1]; aV[2] += Vp[2];
        }
    }
#pragma unroll
    for (int d = 0; d < 3; d++) {
        g_ksum[(b * 96 + lane * 3 + d) * NN + n] = aK[d];
        g_vsum[(b * 96 + lane * 3 + d) * NN + n] = aV[d];
    }
}

// ---------------- phase 3: row-owning moments + eval (192 blocks) ----------
__device__ void row_phase(const float* __restrict__ x,
                          float* __restrict__ out, unsigned char* sm) {
    int row = blockIdx.x;
    if (row >= 192) return;
    int tid = threadIdx.x, wid = tid >> 5, lane = tid & 31;
    float (*s_part)[2 * NCOEF] = (float (*)[2 * NCOEF])sm;
    float* sMo = (float*)(sm + 4 * 2 * NCOEF * 4);
    float* sGo = sMo + NCOEF;

    size_t base = (size_t)row * NN;
    float K[6], V[6];
#pragma unroll
    for (int j = 0; j < 6; j++) {
        size_t idx = base + tid + j * 128;
        K[j] = g_ksum[idx];
        V[j] = g_vsum[idx];
    }
    float M[NCOEF], G[NCOEF];
    float p[6] = {1.f, 1.f, 1.f, 1.f, 1.f, 1.f};
#pragma unroll
    for (int jj = 0; jj < NCOEF; jj++) {
        M[jj] = ((p[0] + p[1]) + (p[2] + p[3])) + (p[4] + p[5]);
        float g01 = fmaf(V[0], p[0], V[1] * p[1]);
        float g23 = fmaf(V[2], p[2], V[3] * p[3]);
        float g45 = fmaf(V[4], p[4], V[5] * p[5]);
        G[jj] = (g01 + g23) + g45;
#pragma unroll
        for (int j = 0; j < 6; j++) p[j] *= K[j];
    }
#pragma unroll
    for (int jj = 0; jj < NCOEF; jj++) {
#pragma unroll
        for (int off = 16; off; off >>= 1) {
            M[jj] += __shfl_xor_sync(0xffffffffu, M[jj], off);
            G[jj] += __shfl_xor_sync(0xffffffffu, G[jj], off);
        }
    }
    if (lane == 0) {
#pragma unroll
        for (int jj = 0; jj < NCOEF; jj++) {
            s_part[wid][jj] = M[jj];
            s_part[wid][NCOEF + jj] = G[jj];
        }
    }
    __syncthreads();
    if (tid < 2 * NCOEF) {
        float s = s_part[0][tid] + s_part[1][tid] + s_part[2][tid] + s_part[3][tid];
        if (tid < NCOEF) sMo[tid] = s * c_invf[tid];
        else sGo[tid - NCOEF] = s * c_invf[tid - NCOEF];
    }
    __syncthreads();
    float cM[NCOEF], cG[NCOEF];
#pragma unroll
    for (int jj = 0; jj < NCOEF; jj++) { cM[jj] = sMo[jj]; cG[jj] = sGo[jj]; }

    const float scale = 0.10206207262f;  // 1/sqrt(96)
#pragma unroll
    for (int j = 0; j < 6; j++) {
        size_t idx = base + tid + j * 128;
        float t = g_qx[idx] * scale;
        float den = cM[NCOEF - 1], num = cG[NCOEF - 1];
#pragma unroll
        for (int jj = NCOEF - 2; jj >= 0; jj--) {
            den = fmaf(den, t, cM[jj]);
            num = fmaf(num, t, cG[jj]);
        }
        out[idx] = x[idx] + num / den;
    }
}

// ---------------- fused mega-kernel ----------------------------------------
__global__ void __launch_bounds__(TPB, 4)
fused_kernel(const float* __restrict__ x, const float* __restrict__ y,
             const float* __restrict__ Wqf, const float* __restrict__ Wqd,
             const float* __restrict__ Wkf, const float* __restrict__ Wkd,
             const float* __restrict__ Wvf, const float* __restrict__ Wvd,
             float* __restrict__ out) {
    __shared__ __align__(16) unsigned char sm[44032];

    int u = blockIdx.x;
    if (u < 312) {
        gram_unit(u, y, sm);
    } else {
        for (int pu = u - 312; pu < 384; pu += 264)
            pre_unit(pu, x, y, Wqf, Wqd, Wkf, Wkd, Wvf, Wvd, sm);
    }
    grid_bar();
    knn_phase();
    grid_bar();
    row_phase(x, out, sm);
}

// ---------------- launcher --------------------------------------------------
extern "C" void kernel_launch(void* const* d_in, const int* in_sizes, int n_in,
                              void* d_out, int out_size) {
    const float* x   = (const float*)d_in[0];
    const float* y   = (const float*)d_in[1];
    const float* Wqf = (const float*)d_in[2];
    const float* Wqd = (const float*)d_in[3];
    const float* Wkf = (const float*)d_in[4];
    const float* Wkd = (const float*)d_in[5];
    const float* Wvf = (const float*)d_in[6];
    const float* Wvd = (const float*)d_in[7];
    float* out = (float*)d_out;

    fused_kernel<<<GRID, TPB>>>(x, y, Wqf, Wqd, Wkf, Wkd, Wvf, Wvd, out);
}